// round 9
// baseline (speedup 1.0000x reference)
#include <cuda_runtime.h>
#include <cuda_fp16.h>
#include <cstdint>

// ============================================================================
// EdgeFeatures: out[i] = (e[i] @ Us_w^T + Us_b) + Vx[src[i]] + Vx[dst[i]]
//   where Vx = x @ Vs_w^T + Vs_b
//
// mma.sync.m16n8k16 fp16 (fp32 accum), split-precision hi/lo (3 passes:
// Ah*Bh + Ah*Bl + Al*Bh, residual ~2^-22), ldmatrix + SW128 smem,
// cp.async for weights, register-prefetch pipeline for activations,
// fused gather epilogue.
//
// NOTE: edge_index is int32 (JAX downcasts int64 with x64 disabled).
// NOTE: __device__ symbols are referenced ONLY in device code (host-side
//       decay of a __device__ array gives the host shadow address, which on
//       GB300 is ATS-readable -> silent zeros. That was the R8 bug.)
// ============================================================================

#define HDIM 256
#define BM 128
#define BK 64          // K elems per chunk = 128 bytes of fp16 = SW128 atom row
#define NCHUNK 4       // 256 / 64
#define NTHREADS 256   // 8 warps: 2 (M) x 4 (N), 64x64 per warp

// smem stage layout (offsets within one stage)
#define A_HI 0          // 128 x 64 fp16 = 16384 B
#define A_LO 16384
#define B_HI 32768      // 256 x 64 fp16 = 32768 B
#define B_LO 65536
#define STAGE_BYTES 98304
#define SMEM_ALLOC (2 * STAGE_BYTES + 1024)

// -------------------------- device scratch ---------------------------------
__device__ float g_Vx[10112 * 256];               // Vx table (V <= 10112)
__device__ __half g_Whi[2][256 * 256];            // [0]=Us_w, [1]=Vs_w (hi)
__device__ __half g_Wlo[2][256 * 256];            // residuals (lo)

// -------------------------- helpers ----------------------------------------
__device__ __forceinline__ uint32_t smem_u32(const void* p) {
    uint32_t a;
    asm("{ .reg .u64 t; cvta.to.shared.u64 t, %1; cvt.u32.u64 %0, t; }"
        : "=r"(a) : "l"(p));
    return a;
}

__device__ __forceinline__ uint32_t sw128(uint32_t off) {
    return off ^ ((off >> 3) & 0x70);
}

__device__ __forceinline__ uint32_t packh(__half a, __half b) {
    return (uint32_t)__half_as_ushort(a) | ((uint32_t)__half_as_ushort(b) << 16);
}

#define LDSM4(r0, r1, r2, r3, addr) \
    asm volatile("ldmatrix.sync.aligned.m8n8.x4.shared.b16 {%0,%1,%2,%3}, [%4];" \
                 : "=r"(r0), "=r"(r1), "=r"(r2), "=r"(r3) : "r"(addr))

#define MMA16816(c, a, b0, b1) \
    asm volatile("mma.sync.aligned.m16n8k16.row.col.f32.f16.f16.f32 " \
                 "{%0,%1,%2,%3}, {%4,%5,%6,%7}, {%8,%9}, {%0,%1,%2,%3};" \
                 : "+f"((c)[0]), "+f"((c)[1]), "+f"((c)[2]), "+f"((c)[3]) \
                 : "r"((a)[0]), "r"((a)[1]), "r"((a)[2]), "r"((a)[3]), \
                   "r"(b0), "r"(b1))

#define CPASYNC16(dst, src) \
    asm volatile("cp.async.cg.shared.global [%0], [%1], 16;" \
                 :: "r"(dst), "l"(src))
#define CP_COMMIT() asm volatile("cp.async.commit_group;" ::: "memory")
#define CP_WAIT0()  asm volatile("cp.async.wait_group 0;" ::: "memory")

// -------------------------- weight conversion ------------------------------
__global__ void convert_weights_kernel(const float* __restrict__ us,
                                       const float* __restrict__ vs) {
    int i = blockIdx.x * blockDim.x + threadIdx.x;
    if (i < 256 * 256) {
        float a = us[i];
        __half h = __float2half_rn(a);
        g_Whi[0][i] = h;
        g_Wlo[0][i] = __float2half_rn(a - __half2float(h));
        float b = vs[i];
        __half h2 = __float2half_rn(b);
        g_Whi[1][i] = h2;
        g_Wlo[1][i] = __float2half_rn(b - __half2float(h2));
    }
}

// -------------------------- pipeline pieces --------------------------------
__device__ __forceinline__ void prefetch_A(const float* __restrict__ A, int Mtot,
                                           int m0, int kc, int tid, float4* apf) {
    const int k0 = kc * BK;
#pragma unroll
    for (int i = 0; i < 8; i++) {
        int q = tid + i * NTHREADS;     // 0..2047
        int row = q >> 4;               // 16 float4 per 64-elem row
        int c4 = q & 15;
        if (m0 + row < Mtot)
            apf[i] = *(const float4*)(A + (size_t)(m0 + row) * HDIM + k0 + c4 * 4);
        else
            apf[i] = make_float4(0.f, 0.f, 0.f, 0.f);
    }
}

__device__ __forceinline__ void sts_A(uint32_t stage, int tid, const float4* apf) {
#pragma unroll
    for (int i = 0; i < 8; i++) {
        int q = tid + i * NTHREADS;
        int row = q >> 4;
        int c4 = q & 15;
        float4 a = apf[i];
        __half hx = __float2half_rn(a.x), hy = __float2half_rn(a.y);
        __half hz = __float2half_rn(a.z), hw = __float2half_rn(a.w);
        uint32_t h0 = packh(hx, hy), h1 = packh(hz, hw);
        uint32_t l0 = packh(__float2half_rn(a.x - __half2float(hx)),
                            __float2half_rn(a.y - __half2float(hy)));
        uint32_t l1 = packh(__float2half_rn(a.z - __half2float(hz)),
                            __float2half_rn(a.w - __half2float(hw)));
        uint32_t off = sw128((uint32_t)(row * 128 + c4 * 8));
        asm volatile("st.shared.v2.u32 [%0], {%1,%2};"
                     :: "r"(stage + A_HI + off), "r"(h0), "r"(h1));
        asm volatile("st.shared.v2.u32 [%0], {%1,%2};"
                     :: "r"(stage + A_LO + off), "r"(l0), "r"(l1));
    }
}

__device__ __forceinline__ void cp_B(uint32_t stage, int kc, int tid,
                                     const __half* __restrict__ Whi,
                                     const __half* __restrict__ Wlo) {
    const int k0 = kc * BK;
#pragma unroll
    for (int i = 0; i < 8; i++) {
        int g = tid + i * NTHREADS;     // 0..2047: 256 rows x 8 granules
        int row = g >> 3;
        int gb = g & 7;
        uint32_t off = sw128((uint32_t)(row * 128 + gb * 16));
        const size_t src = (size_t)row * HDIM + k0 + gb * 8;
        CPASYNC16(stage + B_HI + off, Whi + src);
        CPASYNC16(stage + B_LO + off, Wlo + src);
    }
}

__device__ __forceinline__ void mma_stage(uint32_t stage, int m0w, int n0w,
                                          int lid, float acc[4][8][4]) {
    // ldmatrix lane addressing: lanes 0-7 -> matrix0 rows, 8-15 -> +8 rows,
    // 16-23 -> k+8 (same rows), 24-31 -> +8 rows & k+8.
    const int lrow = (lid & 7) + ((lid >> 3) & 1) * 8;
    const int kb = ((lid >> 4) & 1) * 16;     // byte offset within row
#pragma unroll
    for (int ks = 0; ks < 4; ks++) {
        uint32_t ah[4][4], al[4][4];
#pragma unroll
        for (int mf = 0; mf < 4; mf++) {
            uint32_t off = sw128((uint32_t)((m0w + mf * 16 + lrow) * 128 + ks * 32 + kb));
            LDSM4(ah[mf][0], ah[mf][1], ah[mf][2], ah[mf][3], stage + A_HI + off);
            LDSM4(al[mf][0], al[mf][1], al[mf][2], al[mf][3], stage + A_LO + off);
        }
#pragma unroll
        for (int np = 0; np < 4; np++) {
            uint32_t boff = sw128((uint32_t)((n0w + np * 16 + lrow) * 128 + ks * 32 + kb));
            uint32_t bh0, bh1, bh2, bh3, bl0, bl1, bl2, bl3;
            LDSM4(bh0, bh1, bh2, bh3, stage + B_HI + boff);
            LDSM4(bl0, bl1, bl2, bl3, stage + B_LO + boff);
#pragma unroll
            for (int mf = 0; mf < 4; mf++) {
                MMA16816(acc[mf][2 * np],     ah[mf], bh0, bh2);
                MMA16816(acc[mf][2 * np + 1], ah[mf], bh1, bh3);
                MMA16816(acc[mf][2 * np],     ah[mf], bl0, bl2);
                MMA16816(acc[mf][2 * np + 1], ah[mf], bl1, bl3);
                MMA16816(acc[mf][2 * np],     al[mf], bh0, bh2);
                MMA16816(acc[mf][2 * np + 1], al[mf], bh1, bh3);
            }
        }
    }
}

// -------------------------- main kernel ------------------------------------
// widx selects the weight set (0 = Us, 1 = Vs) via device-side symbol access.
template <bool GATHER>
__global__ void __launch_bounds__(NTHREADS, 1)
edgefeat_kernel(const float* __restrict__ A, int Mtot, int widx,
                const float* __restrict__ bias,
                const int* __restrict__ eidx, int Etot,
                float* __restrict__ out_g)
{
    extern __shared__ char smem_raw[];
    const uint32_t base = (smem_u32(smem_raw) + 1023u) & ~1023u;
    const uint32_t stg0 = base, stg1 = base + STAGE_BYTES;

    const __half* __restrict__ Whi = g_Whi[widx];   // device-side symbol ref
    const __half* __restrict__ Wlo = g_Wlo[widx];

    const int tid = threadIdx.x;
    const int wid = tid >> 5;
    const int lid = tid & 31;
    const int m0 = blockIdx.x * BM;
    const int m0w = (wid & 1) * 64;
    const int n0w = (wid >> 1) * 64;

    float acc[4][8][4];
#pragma unroll
    for (int a = 0; a < 4; a++)
#pragma unroll
        for (int b = 0; b < 8; b++)
#pragma unroll
            for (int c = 0; c < 4; c++) acc[a][b][c] = 0.f;

    float4 apf[8];

    // prologue: chunk 0
    prefetch_A(A, Mtot, m0, 0, tid, apf);
    cp_B(stg0, 0, tid, Whi, Wlo);
    CP_COMMIT();
    sts_A(stg0, tid, apf);
    CP_WAIT0();
    __syncthreads();

#pragma unroll 1
    for (int kc = 0; kc < NCHUNK; kc++) {
        const uint32_t cur = (kc & 1) ? stg1 : stg0;
        const uint32_t nxt = (kc & 1) ? stg0 : stg1;
        if (kc + 1 < NCHUNK) {
            prefetch_A(A, Mtot, m0, kc + 1, tid, apf);
            cp_B(nxt, kc + 1, tid, Whi, Wlo);
            CP_COMMIT();
        }
        mma_stage(cur, m0w, n0w, lid, acc);
        if (kc + 1 < NCHUNK) {
            sts_A(nxt, tid, apf);
            CP_WAIT0();
        }
        __syncthreads();
    }

    // epilogue: accs in registers -> bias (+ gather) -> gmem, float2 stores
    const int tq = lid & 3;        // column-pair index
    const int trow = lid >> 2;     // 0..7
    float2 biasr[8];
#pragma unroll
    for (int nf = 0; nf < 8; nf++)
        biasr[nf] = *(const float2*)(bias + n0w + nf * 8 + 2 * tq);

#pragma unroll
    for (int mf = 0; mf < 4; mf++) {
#pragma unroll
        for (int h = 0; h < 2; h++) {
            const int row = m0 + m0w + mf * 16 + trow + 8 * h;
            if (row < Mtot) {
                const float* vs = g_Vx;
                const float* vd = g_Vx;
                if (GATHER) {
                    int s = eidx[row];
                    int d = eidx[(size_t)Etot + row];
                    vs = g_Vx + (size_t)s * HDIM;
                    vd = g_Vx + (size_t)d * HDIM;
                }
                float* op = (GATHER ? out_g : g_Vx) + (size_t)row * HDIM;
#pragma unroll
                for (int nf = 0; nf < 8; nf++) {
                    const int c = n0w + nf * 8 + 2 * tq;
                    float vx = acc[mf][nf][2 * h + 0] + biasr[nf].x;
                    float vy = acc[mf][nf][2 * h + 1] + biasr[nf].y;
                    if (GATHER) {
                        float2 s2 = *(const float2*)(vs + c);
                        float2 d2 = *(const float2*)(vd + c);
                        vx += s2.x + d2.x;
                        vy += s2.y + d2.y;
                    }
                    *(float2*)(op + c) = make_float2(vx, vy);
                }
            }
        }
    }
}

// -------------------------- launch -----------------------------------------
extern "C" void kernel_launch(void* const* d_in, const int* in_sizes, int n_in,
                              void* d_out, int out_size) {
    const float* x    = (const float*)d_in[0];
    const float* e    = (const float*)d_in[1];
    const int*   eidx = (const int*)d_in[2];      // int32! (JAX x64 disabled)
    const float* Us_w = (const float*)d_in[3];
    const float* Us_b = (const float*)d_in[4];
    const float* Vs_w = (const float*)d_in[5];
    const float* Vs_b = (const float*)d_in[6];
    float*       out  = (float*)d_out;

    const int V = in_sizes[0] / HDIM;   // 10000
    const int E = in_sizes[1] / HDIM;   // 300000

    cudaFuncSetAttribute(edgefeat_kernel<false>,
                         cudaFuncAttributeMaxDynamicSharedMemorySize, SMEM_ALLOC);
    cudaFuncSetAttribute(edgefeat_kernel<true>,
                         cudaFuncAttributeMaxDynamicSharedMemorySize, SMEM_ALLOC);

    convert_weights_kernel<<<256, 256>>>(Us_w, Vs_w);

    // Vx = x @ Vs_w^T + Vs_b  -> g_Vx   (weight set 1)
    edgefeat_kernel<false><<<(V + BM - 1) / BM, NTHREADS, SMEM_ALLOC>>>(
        x, V, 1, Vs_b, nullptr, 0, nullptr);

    // out = e @ Us_w^T + Us_b + Vx[src] + Vx[dst]   (weight set 0)
    edgefeat_kernel<true><<<(E + BM - 1) / BM, NTHREADS, SMEM_ALLOC>>>(
        e, E, 0, Us_b, eidx, E, out);
}

// round 11
// speedup vs baseline: 1.2250x; 1.2250x over previous
#include <cuda_runtime.h>
#include <cuda_fp16.h>
#include <cstdint>

// ============================================================================
// EdgeFeatures: out[i] = (e[i] @ Us_w^T + Us_b) + Vx[src[i]] + Vx[dst[i]]
//   where Vx = x @ Vs_w^T + Vs_b
//
// mma.sync.m16n8k16 fp16 (fp32 accum), 2-pass split precision:
//   A in fp16 (single), B = Bh + Bl (hi/lo fp16 split, near-exact).
//   out = Ah*Bh + Ah*Bl  -> error = A quantization only, rms ~1e-4.
// ldmatrix + SW128 smem, cp.async weights, register-prefetch activations,
// fused gather epilogue.
//
// NOTE: edge_index is int32 (JAX downcasts int64 with x64 disabled).
// NOTE: __device__ symbols referenced ONLY in device code (host-side decay
//       gives the host shadow address -> ATS-readable zeros on GB300).
// ============================================================================

#define HDIM 256
#define BM 128
#define BK 64          // K elems per chunk = 128 bytes of fp16 = SW128 atom row
#define NCHUNK 4       // 256 / 64
#define NTHREADS 256   // 8 warps: 2 (M) x 4 (N), 64x64 per warp

// smem stage layout (offsets within one stage)
#define A_HI 0          // 128 x 64 fp16 = 16384 B
#define B_HI 16384      // 256 x 64 fp16 = 32768 B
#define B_LO 49152
#define STAGE_BYTES 81920
#define SMEM_ALLOC (2 * STAGE_BYTES + 1024)

// -------------------------- device scratch ---------------------------------
__device__ float g_Vx[10112 * 256];               // Vx table (V <= 10112)
__device__ __half g_Whi[2][256 * 256];            // [0]=Us_w, [1]=Vs_w (hi)
__device__ __half g_Wlo[2][256 * 256];            // residuals (lo)

// -------------------------- helpers ----------------------------------------
__device__ __forceinline__ uint32_t smem_u32(const void* p) {
    uint32_t a;
    asm("{ .reg .u64 t; cvta.to.shared.u64 t, %1; cvt.u32.u64 %0, t; }"
        : "=r"(a) : "l"(p));
    return a;
}

__device__ __forceinline__ uint32_t sw128(uint32_t off) {
    return off ^ ((off >> 3) & 0x70);
}

__device__ __forceinline__ uint32_t packh(__half a, __half b) {
    return (uint32_t)__half_as_ushort(a) | ((uint32_t)__half_as_ushort(b) << 16);
}

#define LDSM4(r0, r1, r2, r3, addr) \
    asm volatile("ldmatrix.sync.aligned.m8n8.x4.shared.b16 {%0,%1,%2,%3}, [%4];" \
                 : "=r"(r0), "=r"(r1), "=r"(r2), "=r"(r3) : "r"(addr))

#define MMA16816(c, a, b0, b1) \
    asm volatile("mma.sync.aligned.m16n8k16.row.col.f32.f16.f16.f32 " \
                 "{%0,%1,%2,%3}, {%4,%5,%6,%7}, {%8,%9}, {%0,%1,%2,%3};" \
                 : "+f"((c)[0]), "+f"((c)[1]), "+f"((c)[2]), "+f"((c)[3]) \
                 : "r"((a)[0]), "r"((a)[1]), "r"((a)[2]), "r"((a)[3]), \
                   "r"(b0), "r"(b1))

#define CPASYNC16(dst, src) \
    asm volatile("cp.async.cg.shared.global [%0], [%1], 16;" \
                 :: "r"(dst), "l"(src))
#define CP_COMMIT() asm volatile("cp.async.commit_group;" ::: "memory")
#define CP_WAIT0()  asm volatile("cp.async.wait_group 0;" ::: "memory")

// -------------------------- weight conversion ------------------------------
__global__ void convert_weights_kernel(const float* __restrict__ us,
                                       const float* __restrict__ vs) {
    int i = blockIdx.x * blockDim.x + threadIdx.x;
    if (i < 256 * 256) {
        float a = us[i];
        __half h = __float2half_rn(a);
        g_Whi[0][i] = h;
        g_Wlo[0][i] = __float2half_rn(a - __half2float(h));
        float b = vs[i];
        __half h2 = __float2half_rn(b);
        g_Whi[1][i] = h2;
        g_Wlo[1][i] = __float2half_rn(b - __half2float(h2));
    }
}

// -------------------------- pipeline pieces --------------------------------
__device__ __forceinline__ void prefetch_A(const float* __restrict__ A, int Mtot,
                                           int m0, int kc, int tid, float4* apf) {
    const int k0 = kc * BK;
#pragma unroll
    for (int i = 0; i < 8; i++) {
        int q = tid + i * NTHREADS;     // 0..2047
        int row = q >> 4;               // 16 float4 per 64-elem row
        int c4 = q & 15;
        if (m0 + row < Mtot)
            apf[i] = *(const float4*)(A + (size_t)(m0 + row) * HDIM + k0 + c4 * 4);
        else
            apf[i] = make_float4(0.f, 0.f, 0.f, 0.f);
    }
}

__device__ __forceinline__ void sts_A(uint32_t stage, int tid, const float4* apf) {
#pragma unroll
    for (int i = 0; i < 8; i++) {
        int q = tid + i * NTHREADS;
        int row = q >> 4;
        int c4 = q & 15;
        float4 a = apf[i];
        uint32_t h0 = packh(__float2half_rn(a.x), __float2half_rn(a.y));
        uint32_t h1 = packh(__float2half_rn(a.z), __float2half_rn(a.w));
        uint32_t off = sw128((uint32_t)(row * 128 + c4 * 8));
        asm volatile("st.shared.v2.u32 [%0], {%1,%2};"
                     :: "r"(stage + A_HI + off), "r"(h0), "r"(h1));
    }
}

__device__ __forceinline__ void cp_B(uint32_t stage, int kc, int tid,
                                     const __half* __restrict__ Whi,
                                     const __half* __restrict__ Wlo) {
    const int k0 = kc * BK;
#pragma unroll
    for (int i = 0; i < 8; i++) {
        int g = tid + i * NTHREADS;     // 0..2047: 256 rows x 8 granules
        int row = g >> 3;
        int gb = g & 7;
        uint32_t off = sw128((uint32_t)(row * 128 + gb * 16));
        const size_t src = (size_t)row * HDIM + k0 + gb * 8;
        CPASYNC16(stage + B_HI + off, Whi + src);
        CPASYNC16(stage + B_LO + off, Wlo + src);
    }
}

__device__ __forceinline__ void mma_stage(uint32_t stage, int m0w, int n0w,
                                          int lid, float acc[4][8][4]) {
    // ldmatrix lane addressing: lanes 0-7 -> matrix0 rows, 8-15 -> +8 rows,
    // 16-23 -> k+8 (same rows), 24-31 -> +8 rows & k+8.
    const int lrow = (lid & 7) + ((lid >> 3) & 1) * 8;
    const int kb = ((lid >> 4) & 1) * 16;     // byte offset within row
#pragma unroll
    for (int ks = 0; ks < 4; ks++) {
        uint32_t ah[4][4];
#pragma unroll
        for (int mf = 0; mf < 4; mf++) {
            uint32_t off = sw128((uint32_t)((m0w + mf * 16 + lrow) * 128 + ks * 32 + kb));
            LDSM4(ah[mf][0], ah[mf][1], ah[mf][2], ah[mf][3], stage + A_HI + off);
        }
#pragma unroll
        for (int np = 0; np < 4; np++) {
            uint32_t boff = sw128((uint32_t)((n0w + np * 16 + lrow) * 128 + ks * 32 + kb));
            uint32_t bh0, bh1, bh2, bh3, bl0, bl1, bl2, bl3;
            LDSM4(bh0, bh1, bh2, bh3, stage + B_HI + boff);
            LDSM4(bl0, bl1, bl2, bl3, stage + B_LO + boff);
#pragma unroll
            for (int mf = 0; mf < 4; mf++) {
                MMA16816(acc[mf][2 * np],     ah[mf], bh0, bh2);
                MMA16816(acc[mf][2 * np + 1], ah[mf], bh1, bh3);
                MMA16816(acc[mf][2 * np],     ah[mf], bl0, bl2);
                MMA16816(acc[mf][2 * np + 1], ah[mf], bl1, bl3);
            }
        }
    }
}

// -------------------------- main kernel ------------------------------------
// widx selects the weight set (0 = Us, 1 = Vs) via device-side symbol access.
template <bool GATHER>
__global__ void __launch_bounds__(NTHREADS, 1)
edgefeat_kernel(const float* __restrict__ A, int Mtot, int widx,
                const float* __restrict__ bias,
                const int* __restrict__ eidx, int Etot,
                float* __restrict__ out_g)
{
    extern __shared__ char smem_raw[];
    const uint32_t base = (smem_u32(smem_raw) + 1023u) & ~1023u;
    const uint32_t stg0 = base, stg1 = base + STAGE_BYTES;

    const __half* __restrict__ Whi = g_Whi[widx];   // device-side symbol ref
    const __half* __restrict__ Wlo = g_Wlo[widx];

    const int tid = threadIdx.x;
    const int wid = tid >> 5;
    const int lid = tid & 31;
    const int m0 = blockIdx.x * BM;
    const int m0w = (wid & 1) * 64;
    const int n0w = (wid >> 1) * 64;

    float acc[4][8][4];
#pragma unroll
    for (int a = 0; a < 4; a++)
#pragma unroll
        for (int b = 0; b < 8; b++)
#pragma unroll
            for (int c = 0; c < 4; c++) acc[a][b][c] = 0.f;

    float4 apf[8];

    // prologue: chunk 0
    prefetch_A(A, Mtot, m0, 0, tid, apf);
    cp_B(stg0, 0, tid, Whi, Wlo);
    CP_COMMIT();
    sts_A(stg0, tid, apf);
    CP_WAIT0();
    __syncthreads();

#pragma unroll 1
    for (int kc = 0; kc < NCHUNK; kc++) {
        const uint32_t cur = (kc & 1) ? stg1 : stg0;
        const uint32_t nxt = (kc & 1) ? stg0 : stg1;
        if (kc + 1 < NCHUNK) {
            prefetch_A(A, Mtot, m0, kc + 1, tid, apf);
            cp_B(nxt, kc + 1, tid, Whi, Wlo);
            CP_COMMIT();
        }
        mma_stage(cur, m0w, n0w, lid, acc);
        if (kc + 1 < NCHUNK) {
            sts_A(nxt, tid, apf);
            CP_WAIT0();
        }
        __syncthreads();
    }

    // epilogue: accs in registers -> bias (+ gather) -> gmem, float2 stores
    const int tq = lid & 3;        // column-pair index
    const int trow = lid >> 2;     // 0..7
    float2 biasr[8];
#pragma unroll
    for (int nf = 0; nf < 8; nf++)
        biasr[nf] = *(const float2*)(bias + n0w + nf * 8 + 2 * tq);

#pragma unroll
    for (int mf = 0; mf < 4; mf++) {
#pragma unroll
        for (int h = 0; h < 2; h++) {
            const int row = m0 + m0w + mf * 16 + trow + 8 * h;
            if (row < Mtot) {
                const float* vs = g_Vx;
                const float* vd = g_Vx;
                if (GATHER) {
                    int s = eidx[row];
                    int d = eidx[(size_t)Etot + row];
                    vs = g_Vx + (size_t)s * HDIM;
                    vd = g_Vx + (size_t)d * HDIM;
                }
                float* op = (GATHER ? out_g : g_Vx) + (size_t)row * HDIM;
#pragma unroll
                for (int nf = 0; nf < 8; nf++) {
                    const int c = n0w + nf * 8 + 2 * tq;
                    float vx = acc[mf][nf][2 * h + 0] + biasr[nf].x;
                    float vy = acc[mf][nf][2 * h + 1] + biasr[nf].y;
                    if (GATHER) {
                        float2 s2 = *(const float2*)(vs + c);
                        float2 d2 = *(const float2*)(vd + c);
                        vx += s2.x + d2.x;
                        vy += s2.y + d2.y;
                    }
                    *(float2*)(op + c) = make_float2(vx, vy);
                }
            }
        }
    }
}

// -------------------------- launch -----------------------------------------
extern "C" void kernel_launch(void* const* d_in, const int* in_sizes, int n_in,
                              void* d_out, int out_size) {
    const float* x    = (const float*)d_in[0];
    const float* e    = (const float*)d_in[1];
    const int*   eidx = (const int*)d_in[2];      // int32! (JAX x64 disabled)
    const float* Us_w = (const float*)d_in[3];
    const float* Us_b = (const float*)d_in[4];
    const float* Vs_w = (const float*)d_in[5];
    const float* Vs_b = (const float*)d_in[6];
    float*       out  = (float*)d_out;

    const int V = in_sizes[0] / HDIM;   // 10000
    const int E = in_sizes[1] / HDIM;   // 300000

    cudaFuncSetAttribute(edgefeat_kernel<false>,
                         cudaFuncAttributeMaxDynamicSharedMemorySize, SMEM_ALLOC);
    cudaFuncSetAttribute(edgefeat_kernel<true>,
                         cudaFuncAttributeMaxDynamicSharedMemorySize, SMEM_ALLOC);

    convert_weights_kernel<<<256, 256>>>(Us_w, Vs_w);

    // Vx = x @ Vs_w^T + Vs_b  -> g_Vx   (weight set 1)
    edgefeat_kernel<false><<<(V + BM - 1) / BM, NTHREADS, SMEM_ALLOC>>>(
        x, V, 1, Vs_b, nullptr, 0, nullptr);

    // out = e @ Us_w^T + Us_b + Vx[src] + Vx[dst]   (weight set 0)
    edgefeat_kernel<true><<<(E + BM - 1) / BM, NTHREADS, SMEM_ALLOC>>>(
        e, E, 0, Us_b, eidx, E, out);
}

// round 12
// speedup vs baseline: 1.4984x; 1.2232x over previous
#include <cuda_runtime.h>
#include <cuda_fp16.h>
#include <cstdint>

// ============================================================================
// EdgeFeatures: out[i] = (e[i] @ Us_w^T + Us_b) + Vx[src[i]] + Vx[dst[i]]
//   where Vx = x @ Vs_w^T + Vs_b
//
// Single-pass fp16 mma.sync.m16n8k16 (fp32 accum). Combined A+B fp16
// quantization error ~3e-4 rms (measured A-only: 2.07e-4), threshold 1e-3.
// ldmatrix + SW128 smem, cp.async weights, register-prefetch activations,
// fused gather epilogue.
//
// NOTE: edge_index is int32 (JAX downcasts int64 with x64 disabled).
// NOTE: __device__ symbols referenced ONLY in device code (host-side decay
//       gives the host shadow address -> ATS-readable zeros on GB300).
// ============================================================================

#define HDIM 256
#define BM 128
#define BK 64          // K elems per chunk = 128 bytes of fp16 = SW128 atom row
#define NCHUNK 4       // 256 / 64
#define NTHREADS 256   // 8 warps: 2 (M) x 4 (N), 64x64 per warp

// smem stage layout (offsets within one stage)
#define A_HI 0          // 128 x 64 fp16 = 16384 B
#define B_HI 16384      // 256 x 64 fp16 = 32768 B
#define STAGE_BYTES 49152
#define SMEM_ALLOC (2 * STAGE_BYTES + 1024)

// -------------------------- device scratch ---------------------------------
__device__ float g_Vx[10112 * 256];               // Vx table (V <= 10112)
__device__ __half g_Whi[2][256 * 256];            // [0]=Us_w, [1]=Vs_w (fp16)

// -------------------------- helpers ----------------------------------------
__device__ __forceinline__ uint32_t smem_u32(const void* p) {
    uint32_t a;
    asm("{ .reg .u64 t; cvta.to.shared.u64 t, %1; cvt.u32.u64 %0, t; }"
        : "=r"(a) : "l"(p));
    return a;
}

__device__ __forceinline__ uint32_t sw128(uint32_t off) {
    return off ^ ((off >> 3) & 0x70);
}

__device__ __forceinline__ uint32_t packh(__half a, __half b) {
    return (uint32_t)__half_as_ushort(a) | ((uint32_t)__half_as_ushort(b) << 16);
}

#define LDSM4(r0, r1, r2, r3, addr) \
    asm volatile("ldmatrix.sync.aligned.m8n8.x4.shared.b16 {%0,%1,%2,%3}, [%4];" \
                 : "=r"(r0), "=r"(r1), "=r"(r2), "=r"(r3) : "r"(addr))

#define MMA16816(c, a, b0, b1) \
    asm volatile("mma.sync.aligned.m16n8k16.row.col.f32.f16.f16.f32 " \
                 "{%0,%1,%2,%3}, {%4,%5,%6,%7}, {%8,%9}, {%0,%1,%2,%3};" \
                 : "+f"((c)[0]), "+f"((c)[1]), "+f"((c)[2]), "+f"((c)[3]) \
                 : "r"((a)[0]), "r"((a)[1]), "r"((a)[2]), "r"((a)[3]), \
                   "r"(b0), "r"(b1))

#define CPASYNC16(dst, src) \
    asm volatile("cp.async.cg.shared.global [%0], [%1], 16;" \
                 :: "r"(dst), "l"(src))
#define CP_COMMIT() asm volatile("cp.async.commit_group;" ::: "memory")
#define CP_WAIT0()  asm volatile("cp.async.wait_group 0;" ::: "memory")

// -------------------------- weight conversion ------------------------------
__global__ void convert_weights_kernel(const float* __restrict__ us,
                                       const float* __restrict__ vs) {
    int i = blockIdx.x * blockDim.x + threadIdx.x;
    if (i < 256 * 256) {
        g_Whi[0][i] = __float2half_rn(us[i]);
        g_Whi[1][i] = __float2half_rn(vs[i]);
    }
}

// -------------------------- pipeline pieces --------------------------------
__device__ __forceinline__ void prefetch_A(const float* __restrict__ A, int Mtot,
                                           int m0, int kc, int tid, float4* apf) {
    const int k0 = kc * BK;
#pragma unroll
    for (int i = 0; i < 8; i++) {
        int q = tid + i * NTHREADS;     // 0..2047
        int row = q >> 4;               // 16 float4 per 64-elem row
        int c4 = q & 15;
        if (m0 + row < Mtot)
            apf[i] = *(const float4*)(A + (size_t)(m0 + row) * HDIM + k0 + c4 * 4);
        else
            apf[i] = make_float4(0.f, 0.f, 0.f, 0.f);
    }
}

__device__ __forceinline__ void sts_A(uint32_t stage, int tid, const float4* apf) {
#pragma unroll
    for (int i = 0; i < 8; i++) {
        int q = tid + i * NTHREADS;
        int row = q >> 4;
        int c4 = q & 15;
        float4 a = apf[i];
        uint32_t h0 = packh(__float2half_rn(a.x), __float2half_rn(a.y));
        uint32_t h1 = packh(__float2half_rn(a.z), __float2half_rn(a.w));
        uint32_t off = sw128((uint32_t)(row * 128 + c4 * 8));
        asm volatile("st.shared.v2.u32 [%0], {%1,%2};"
                     :: "r"(stage + A_HI + off), "r"(h0), "r"(h1));
    }
}

__device__ __forceinline__ void cp_B(uint32_t stage, int kc, int tid,
                                     const __half* __restrict__ Whi) {
    const int k0 = kc * BK;
#pragma unroll
    for (int i = 0; i < 8; i++) {
        int g = tid + i * NTHREADS;     // 0..2047: 256 rows x 8 granules
        int row = g >> 3;
        int gb = g & 7;
        uint32_t off = sw128((uint32_t)(row * 128 + gb * 16));
        CPASYNC16(stage + B_HI + off, Whi + (size_t)row * HDIM + k0 + gb * 8);
    }
}

__device__ __forceinline__ void mma_stage(uint32_t stage, int m0w, int n0w,
                                          int lid, float acc[4][8][4]) {
    // ldmatrix lane addressing: lanes 0-7 -> matrix0 rows, 8-15 -> +8 rows,
    // 16-23 -> k+8 (same rows), 24-31 -> +8 rows & k+8.
    const int lrow = (lid & 7) + ((lid >> 3) & 1) * 8;
    const int kb = ((lid >> 4) & 1) * 16;     // byte offset within row
#pragma unroll
    for (int ks = 0; ks < 4; ks++) {
        uint32_t ah[4][4];
#pragma unroll
        for (int mf = 0; mf < 4; mf++) {
            uint32_t off = sw128((uint32_t)((m0w + mf * 16 + lrow) * 128 + ks * 32 + kb));
            LDSM4(ah[mf][0], ah[mf][1], ah[mf][2], ah[mf][3], stage + A_HI + off);
        }
#pragma unroll
        for (int np = 0; np < 4; np++) {
            uint32_t boff = sw128((uint32_t)((n0w + np * 16 + lrow) * 128 + ks * 32 + kb));
            uint32_t bh0, bh1, bh2, bh3;
            LDSM4(bh0, bh1, bh2, bh3, stage + B_HI + boff);
#pragma unroll
            for (int mf = 0; mf < 4; mf++) {
                MMA16816(acc[mf][2 * np],     ah[mf], bh0, bh2);
                MMA16816(acc[mf][2 * np + 1], ah[mf], bh1, bh3);
            }
        }
    }
}

// -------------------------- main kernel ------------------------------------
// widx selects the weight set (0 = Us, 1 = Vs) via device-side symbol access.
template <bool GATHER>
__global__ void __launch_bounds__(NTHREADS, 1)
edgefeat_kernel(const float* __restrict__ A, int Mtot, int widx,
                const float* __restrict__ bias,
                const int* __restrict__ eidx, int Etot,
                float* __restrict__ out_g)
{
    extern __shared__ char smem_raw[];
    const uint32_t base = (smem_u32(smem_raw) + 1023u) & ~1023u;
    const uint32_t stg0 = base, stg1 = base + STAGE_BYTES;

    const __half* __restrict__ Whi = g_Whi[widx];   // device-side symbol ref

    const int tid = threadIdx.x;
    const int wid = tid >> 5;
    const int lid = tid & 31;
    const int m0 = blockIdx.x * BM;
    const int m0w = (wid & 1) * 64;
    const int n0w = (wid >> 1) * 64;

    float acc[4][8][4];
#pragma unroll
    for (int a = 0; a < 4; a++)
#pragma unroll
        for (int b = 0; b < 8; b++)
#pragma unroll
            for (int c = 0; c < 4; c++) acc[a][b][c] = 0.f;

    float4 apf[8];

    // prologue: chunk 0
    prefetch_A(A, Mtot, m0, 0, tid, apf);
    cp_B(stg0, 0, tid, Whi);
    CP_COMMIT();
    sts_A(stg0, tid, apf);
    CP_WAIT0();
    __syncthreads();

#pragma unroll 1
    for (int kc = 0; kc < NCHUNK; kc++) {
        const uint32_t cur = (kc & 1) ? stg1 : stg0;
        const uint32_t nxt = (kc & 1) ? stg0 : stg1;
        if (kc + 1 < NCHUNK) {
            prefetch_A(A, Mtot, m0, kc + 1, tid, apf);
            cp_B(nxt, kc + 1, tid, Whi);
            CP_COMMIT();
        }
        mma_stage(cur, m0w, n0w, lid, acc);
        if (kc + 1 < NCHUNK) {
            sts_A(nxt, tid, apf);
            CP_WAIT0();
        }
        __syncthreads();
    }

    // epilogue: accs in registers -> bias (+ gather) -> gmem, float2 stores
    const int tq = lid & 3;        // column-pair index
    const int trow = lid >> 2;     // 0..7
    float2 biasr[8];
#pragma unroll
    for (int nf = 0; nf < 8; nf++)
        biasr[nf] = *(const float2*)(bias + n0w + nf * 8 + 2 * tq);

#pragma unroll
    for (int mf = 0; mf < 4; mf++) {
#pragma unroll
        for (int h = 0; h < 2; h++) {
            const int row = m0 + m0w + mf * 16 + trow + 8 * h;
            if (row < Mtot) {
                const float* vs = g_Vx;
                const float* vd = g_Vx;
                if (GATHER) {
                    int s = eidx[row];
                    int d = eidx[(size_t)Etot + row];
                    vs = g_Vx + (size_t)s * HDIM;
                    vd = g_Vx + (size_t)d * HDIM;
                }
                float* op = (GATHER ? out_g : g_Vx) + (size_t)row * HDIM;
#pragma unroll
                for (int nf = 0; nf < 8; nf++) {
                    const int c = n0w + nf * 8 + 2 * tq;
                    float vx = acc[mf][nf][2 * h + 0] + biasr[nf].x;
                    float vy = acc[mf][nf][2 * h + 1] + biasr[nf].y;
                    if (GATHER) {
                        float2 s2 = *(const float2*)(vs + c);
                        float2 d2 = *(const float2*)(vd + c);
                        vx += s2.x + d2.x;
                        vy += s2.y + d2.y;
                    }
                    *(float2*)(op + c) = make_float2(vx, vy);
                }
            }
        }
    }
}

// -------------------------- launch -----------------------------------------
extern "C" void kernel_launch(void* const* d_in, const int* in_sizes, int n_in,
                              void* d_out, int out_size) {
    const float* x    = (const float*)d_in[0];
    const float* e    = (const float*)d_in[1];
    const int*   eidx = (const int*)d_in[2];      // int32! (JAX x64 disabled)
    const float* Us_w = (const float*)d_in[3];
    const float* Us_b = (const float*)d_in[4];
    const float* Vs_w = (const float*)d_in[5];
    const float* Vs_b = (const float*)d_in[6];
    float*       out  = (float*)d_out;

    const int V = in_sizes[0] / HDIM;   // 10000
    const int E = in_sizes[1] / HDIM;   // 300000

    cudaFuncSetAttribute(edgefeat_kernel<false>,
                         cudaFuncAttributeMaxDynamicSharedMemorySize, SMEM_ALLOC);
    cudaFuncSetAttribute(edgefeat_kernel<true>,
                         cudaFuncAttributeMaxDynamicSharedMemorySize, SMEM_ALLOC);

    convert_weights_kernel<<<256, 256>>>(Us_w, Vs_w);

    // Vx = x @ Vs_w^T + Vs_b  -> g_Vx   (weight set 1)
    edgefeat_kernel<false><<<(V + BM - 1) / BM, NTHREADS, SMEM_ALLOC>>>(
        x, V, 1, Vs_b, nullptr, 0, nullptr);

    // out = e @ Us_w^T + Us_b + Vx[src] + Vx[dst]   (weight set 0)
    edgefeat_kernel<true><<<(E + BM - 1) / BM, NTHREADS, SMEM_ALLOC>>>(
        e, E, 0, Us_b, eidx, E, out);
}

// round 13
// speedup vs baseline: 2.1166x; 1.4126x over previous
#include <cuda_runtime.h>
#include <cuda_fp16.h>
#include <cstdint>

// ============================================================================
// EdgeFeatures: out[i] = (e[i] @ Us_w^T + Us_b) + Vx[src[i]] + Vx[dst[i]]
//   where Vx = x @ Vs_w^T + Vs_b
//
// Single-pass fp16 mma.sync.m16n8k16 (fp32 accum), rel_err ~2.8e-4.
// BM=64 tile + __launch_bounds__(256,2) -> 2 CTAs/SM so one CTA's mainloop
// hides the other's prologue/epilogue latency (R12 showed ~300us exposed).
// ldmatrix + SW128 smem, cp.async weights, register-prefetch activations,
// fused gather epilogue.
//
// NOTE: edge_index is int32 (JAX downcasts int64 with x64 disabled).
// NOTE: __device__ symbols referenced ONLY in device code (host-side decay
//       gives the host shadow address -> ATS-readable zeros on GB300).
// ============================================================================

#define HDIM 256
#define BM 64
#define BK 64          // K elems per chunk = 128 bytes of fp16 = SW128 atom row
#define NCHUNK 4       // 256 / 64
#define NTHREADS 256   // 8 warps: 1 (M) x 8 (N), 64x32 warp tile

// smem stage layout (offsets within one stage)
#define A_HI 0          // 64 x 64 fp16  = 8192 B
#define B_HI 8192       // 256 x 64 fp16 = 32768 B
#define STAGE_BYTES 40960
#define SMEM_ALLOC (2 * STAGE_BYTES + 1024)

// -------------------------- device scratch ---------------------------------
__device__ float g_Vx[10112 * 256];               // Vx table (V <= 10112)
__device__ __half g_Whi[2][256 * 256];            // [0]=Us_w, [1]=Vs_w (fp16)

// -------------------------- helpers ----------------------------------------
__device__ __forceinline__ uint32_t smem_u32(const void* p) {
    uint32_t a;
    asm("{ .reg .u64 t; cvta.to.shared.u64 t, %1; cvt.u32.u64 %0, t; }"
        : "=r"(a) : "l"(p));
    return a;
}

__device__ __forceinline__ uint32_t sw128(uint32_t off) {
    return off ^ ((off >> 3) & 0x70);
}

__device__ __forceinline__ uint32_t packh(__half a, __half b) {
    return (uint32_t)__half_as_ushort(a) | ((uint32_t)__half_as_ushort(b) << 16);
}

#define LDSM4(r0, r1, r2, r3, addr) \
    asm volatile("ldmatrix.sync.aligned.m8n8.x4.shared.b16 {%0,%1,%2,%3}, [%4];" \
                 : "=r"(r0), "=r"(r1), "=r"(r2), "=r"(r3) : "r"(addr))

#define MMA16816(c, a, b0, b1) \
    asm volatile("mma.sync.aligned.m16n8k16.row.col.f32.f16.f16.f32 " \
                 "{%0,%1,%2,%3}, {%4,%5,%6,%7}, {%8,%9}, {%0,%1,%2,%3};" \
                 : "+f"((c)[0]), "+f"((c)[1]), "+f"((c)[2]), "+f"((c)[3]) \
                 : "r"((a)[0]), "r"((a)[1]), "r"((a)[2]), "r"((a)[3]), \
                   "r"(b0), "r"(b1))

#define CPASYNC16(dst, src) \
    asm volatile("cp.async.cg.shared.global [%0], [%1], 16;" \
                 :: "r"(dst), "l"(src))
#define CP_COMMIT() asm volatile("cp.async.commit_group;" ::: "memory")
#define CP_WAIT0()  asm volatile("cp.async.wait_group 0;" ::: "memory")

// -------------------------- weight conversion ------------------------------
__global__ void convert_weights_kernel(const float* __restrict__ us,
                                       const float* __restrict__ vs) {
    int i = blockIdx.x * blockDim.x + threadIdx.x;
    if (i < 256 * 256) {
        g_Whi[0][i] = __float2half_rn(us[i]);
        g_Whi[1][i] = __float2half_rn(vs[i]);
    }
}

// -------------------------- pipeline pieces --------------------------------
__device__ __forceinline__ void prefetch_A(const float* __restrict__ A, int Mtot,
                                           int m0, int kc, int tid, float4* apf) {
    const int k0 = kc * BK;
#pragma unroll
    for (int i = 0; i < 4; i++) {
        int q = tid + i * NTHREADS;     // 0..1023 (64 rows x 16 float4)
        int row = q >> 4;
        int c4 = q & 15;
        if (m0 + row < Mtot)
            apf[i] = *(const float4*)(A + (size_t)(m0 + row) * HDIM + k0 + c4 * 4);
        else
            apf[i] = make_float4(0.f, 0.f, 0.f, 0.f);
    }
}

__device__ __forceinline__ void sts_A(uint32_t stage, int tid, const float4* apf) {
#pragma unroll
    for (int i = 0; i < 4; i++) {
        int q = tid + i * NTHREADS;
        int row = q >> 4;
        int c4 = q & 15;
        float4 a = apf[i];
        uint32_t h0 = packh(__float2half_rn(a.x), __float2half_rn(a.y));
        uint32_t h1 = packh(__float2half_rn(a.z), __float2half_rn(a.w));
        uint32_t off = sw128((uint32_t)(row * 128 + c4 * 8));
        asm volatile("st.shared.v2.u32 [%0], {%1,%2};"
                     :: "r"(stage + A_HI + off), "r"(h0), "r"(h1));
    }
}

__device__ __forceinline__ void cp_B(uint32_t stage, int kc, int tid,
                                     const __half* __restrict__ Whi) {
    const int k0 = kc * BK;
#pragma unroll
    for (int i = 0; i < 8; i++) {
        int g = tid + i * NTHREADS;     // 0..2047: 256 rows x 8 granules
        int row = g >> 3;
        int gb = g & 7;
        uint32_t off = sw128((uint32_t)(row * 128 + gb * 16));
        CPASYNC16(stage + B_HI + off, Whi + (size_t)row * HDIM + k0 + gb * 8);
    }
}

__device__ __forceinline__ void mma_stage(uint32_t stage, int n0w,
                                          int lid, float acc[4][4][4]) {
    // ldmatrix lane addressing: lanes 0-7 -> matrix0 rows, 8-15 -> +8 rows,
    // 16-23 -> k+8 (same rows), 24-31 -> +8 rows & k+8.
    const int lrow = (lid & 7) + ((lid >> 3) & 1) * 8;
    const int kb = ((lid >> 4) & 1) * 16;     // byte offset within row
#pragma unroll
    for (int ks = 0; ks < 4; ks++) {
        uint32_t ah[4][4];
#pragma unroll
        for (int mf = 0; mf < 4; mf++) {
            uint32_t off = sw128((uint32_t)((mf * 16 + lrow) * 128 + ks * 32 + kb));
            LDSM4(ah[mf][0], ah[mf][1], ah[mf][2], ah[mf][3], stage + A_HI + off);
        }
#pragma unroll
        for (int np = 0; np < 2; np++) {
            uint32_t boff = sw128((uint32_t)((n0w + np * 16 + lrow) * 128 + ks * 32 + kb));
            uint32_t bh0, bh1, bh2, bh3;
            LDSM4(bh0, bh1, bh2, bh3, stage + B_HI + boff);
#pragma unroll
            for (int mf = 0; mf < 4; mf++) {
                MMA16816(acc[mf][2 * np],     ah[mf], bh0, bh2);
                MMA16816(acc[mf][2 * np + 1], ah[mf], bh1, bh3);
            }
        }
    }
}

// -------------------------- main kernel ------------------------------------
// widx selects the weight set (0 = Us, 1 = Vs) via device-side symbol access.
template <bool GATHER>
__global__ void __launch_bounds__(NTHREADS, 2)
edgefeat_kernel(const float* __restrict__ A, int Mtot, int widx,
                const float* __restrict__ bias,
                const int* __restrict__ eidx, int Etot,
                float* __restrict__ out_g)
{
    extern __shared__ char smem_raw[];
    const uint32_t base = (smem_u32(smem_raw) + 1023u) & ~1023u;
    const uint32_t stg0 = base, stg1 = base + STAGE_BYTES;

    const __half* __restrict__ Whi = g_Whi[widx];   // device-side symbol ref

    const int tid = threadIdx.x;
    const int wid = tid >> 5;
    const int lid = tid & 31;
    const int m0 = blockIdx.x * BM;
    const int n0w = wid * 32;           // 8 warps cover N=256

    float acc[4][4][4];
#pragma unroll
    for (int a = 0; a < 4; a++)
#pragma unroll
        for (int b = 0; b < 4; b++)
#pragma unroll
            for (int c = 0; c < 4; c++) acc[a][b][c] = 0.f;

    float4 apf[4];

    // prologue: chunk 0
    prefetch_A(A, Mtot, m0, 0, tid, apf);
    cp_B(stg0, 0, tid, Whi);
    CP_COMMIT();
    sts_A(stg0, tid, apf);
    CP_WAIT0();
    __syncthreads();

#pragma unroll 1
    for (int kc = 0; kc < NCHUNK; kc++) {
        const uint32_t cur = (kc & 1) ? stg1 : stg0;
        const uint32_t nxt = (kc & 1) ? stg0 : stg1;
        if (kc + 1 < NCHUNK) {
            prefetch_A(A, Mtot, m0, kc + 1, tid, apf);
            cp_B(nxt, kc + 1, tid, Whi);
            CP_COMMIT();
        }
        mma_stage(cur, n0w, lid, acc);
        if (kc + 1 < NCHUNK) {
            sts_A(nxt, tid, apf);
            CP_WAIT0();
        }
        __syncthreads();
    }

    // epilogue: accs in registers -> bias (+ gather) -> gmem, float2 stores
    const int tq = lid & 3;        // column-pair index
    const int trow = lid >> 2;     // 0..7
    float2 biasr[4];
#pragma unroll
    for (int nf = 0; nf < 4; nf++)
        biasr[nf] = *(const float2*)(bias + n0w + nf * 8 + 2 * tq);

#pragma unroll
    for (int mf = 0; mf < 4; mf++) {
#pragma unroll
        for (int h = 0; h < 2; h++) {
            const int row = m0 + mf * 16 + trow + 8 * h;
            if (row < Mtot) {
                const float* vs = g_Vx;
                const float* vd = g_Vx;
                if (GATHER) {
                    int s = eidx[row];
                    int d = eidx[(size_t)Etot + row];
                    vs = g_Vx + (size_t)s * HDIM;
                    vd = g_Vx + (size_t)d * HDIM;
                }
                float* op = (GATHER ? out_g : g_Vx) + (size_t)row * HDIM;
#pragma unroll
                for (int nf = 0; nf < 4; nf++) {
                    const int c = n0w + nf * 8 + 2 * tq;
                    float vx = acc[mf][nf][2 * h + 0] + biasr[nf].x;
                    float vy = acc[mf][nf][2 * h + 1] + biasr[nf].y;
                    if (GATHER) {
                        float2 s2 = *(const float2*)(vs + c);
                        float2 d2 = *(const float2*)(vd + c);
                        vx += s2.x + d2.x;
                        vy += s2.y + d2.y;
                    }
                    *(float2*)(op + c) = make_float2(vx, vy);
                }
            }
        }
    }
}

// -------------------------- launch -----------------------------------------
extern "C" void kernel_launch(void* const* d_in, const int* in_sizes, int n_in,
                              void* d_out, int out_size) {
    const float* x    = (const float*)d_in[0];
    const float* e    = (const float*)d_in[1];
    const int*   eidx = (const int*)d_in[2];      // int32! (JAX x64 disabled)
    const float* Us_w = (const float*)d_in[3];
    const float* Us_b = (const float*)d_in[4];
    const float* Vs_w = (const float*)d_in[5];
    const float* Vs_b = (const float*)d_in[6];
    float*       out  = (float*)d_out;

    const int V = in_sizes[0] / HDIM;   // 10000
    const int E = in_sizes[1] / HDIM;   // 300000

    cudaFuncSetAttribute(edgefeat_kernel<false>,
                         cudaFuncAttributeMaxDynamicSharedMemorySize, SMEM_ALLOC);
    cudaFuncSetAttribute(edgefeat_kernel<true>,
                         cudaFuncAttributeMaxDynamicSharedMemorySize, SMEM_ALLOC);

    convert_weights_kernel<<<256, 256>>>(Us_w, Vs_w);

    // Vx = x @ Vs_w^T + Vs_b  -> g_Vx   (weight set 1)
    edgefeat_kernel<false><<<(V + BM - 1) / BM, NTHREADS, SMEM_ALLOC>>>(
        x, V, 1, Vs_b, nullptr, 0, nullptr);

    // out = e @ Us_w^T + Us_b + Vx[src] + Vx[dst]   (weight set 0)
    edgefeat_kernel<true><<<(E + BM - 1) / BM, NTHREADS, SMEM_ALLOC>>>(
        e, E, 0, Us_b, eidx, E, out);
}